// round 3
// baseline (speedup 1.0000x reference)
#include <cuda_runtime.h>
#include <math.h>

// ---------------------------------------------------------------------------
// GCN_47760036331636: 2-layer GCN
//   h1 = agg(x @ W1) + b1 ; relu
//   h2 = agg(relu(h1) @ W2) + b2 ; log_softmax
// agg(h)[i] = sum_{e:dst=i} h[src_e]*dinv[src]*dinv[i]  +  h[i]*dinv[i]^2
// deg[i] = 1 + |{e : dst_e = i}| ; dinv = rsqrt(deg)
//
// NOTE: edge_index dtype is int32 in practice (JAX x64 disabled), but we
// detect int64 vs int32 on-device and normalize to int32 scratch arrays.
// ---------------------------------------------------------------------------

#define NODES  50000
#define EDGES  800000
#define IN_C   512
#define HID_C  256
#define OUT_C  64

// Scratch (allocation-free: __device__ globals)
__device__ int   g_is64;
__device__ int   g_src [EDGES];
__device__ int   g_dst [EDGES];
__device__ float g_norm[EDGES];
__device__ float g_deg [NODES];
__device__ float g_dinv[NODES];
__device__ float g_h1  [(size_t)NODES * HID_C];   // x @ W1
__device__ float g_out1[(size_t)NODES * HID_C];   // aggregated layer-1 (pre-relu)
__device__ float g_h2  [(size_t)NODES * OUT_C];   // relu(out1) @ W2

// ---------------------------------------------------------------------------
// Edge dtype detection + conversion
// ---------------------------------------------------------------------------
__global__ void k_detect(const void* ei, int E, int n) {
    if (blockIdx.x == 0 && threadIdx.x == 0) {
        const unsigned long long* p = (const unsigned long long*)ei;
        int cnt = E < 1024 ? E : 1024;
        int ok64 = 1;
        for (int i = 0; i < cnt; i++) {
            if (p[i] >= (unsigned long long)n) { ok64 = 0; break; }
        }
        g_is64 = ok64;
    }
}

__global__ void k_convert(const void* ei, int E) {
    int e = blockIdx.x * blockDim.x + threadIdx.x;
    if (e >= E) return;
    int s, d;
    if (g_is64) {
        const long long* p = (const long long*)ei;
        s = (int)p[e];
        d = (int)p[E + e];
    } else {
        const int* p = (const int*)ei;
        s = p[e];
        d = p[E + e];
    }
    g_src[e] = s;
    g_dst[e] = d;
}

// ---------------------------------------------------------------------------
// Degree / dinv / per-edge norm
// ---------------------------------------------------------------------------
__global__ void k_deg_init(float* deg, int n) {
    int i = blockIdx.x * blockDim.x + threadIdx.x;
    if (i < n) deg[i] = 1.0f;   // self-loop
}

__global__ void k_deg_count(const int* __restrict__ dst, int E, float* deg) {
    int e = blockIdx.x * blockDim.x + threadIdx.x;
    if (e < E) atomicAdd(deg + dst[e], 1.0f);
}

__global__ void k_dinv(const float* __restrict__ deg, float* __restrict__ dinv, int n) {
    int i = blockIdx.x * blockDim.x + threadIdx.x;
    if (i < n) dinv[i] = rsqrtf(deg[i]);   // deg >= 1 always
}

__global__ void k_norm(const int* __restrict__ src, const int* __restrict__ dst,
                       const float* __restrict__ dinv, float* __restrict__ norm, int E) {
    int e = blockIdx.x * blockDim.x + threadIdx.x;
    if (e < E) norm[e] = dinv[src[e]] * dinv[dst[e]];
}

// ---------------------------------------------------------------------------
// Tiled fp32 GEMM: C[M,N] = A[M,K] @ B[K,N], optional ReLU on A load.
// BM=128 BN=64 BK=16, 256 threads, 8x4 per thread.
// ---------------------------------------------------------------------------
template<int BM, int BN, int BK, int TM, int TN, bool RELU>
__global__ void k_gemm(const float* __restrict__ A, const float* __restrict__ B,
                       float* __restrict__ C, int M, int N, int K)
{
    constexpr int THREADS = (BM / TM) * (BN / TN);
    __shared__ float As[BK][BM + 4];
    __shared__ float Bs[BK][BN];

    const int tid = threadIdx.x;
    const int tx  = tid % (BN / TN);
    const int ty  = tid / (BN / TN);
    const int rowBase = blockIdx.y * BM;
    const int colBase = blockIdx.x * BN;

    float acc[TM][TN];
    #pragma unroll
    for (int i = 0; i < TM; i++)
        #pragma unroll
        for (int j = 0; j < TN; j++) acc[i][j] = 0.0f;

    for (int k0 = 0; k0 < K; k0 += BK) {
        constexpr int AVEC = BM * BK / 4;
        #pragma unroll
        for (int l = 0; l < AVEC / THREADS; l++) {
            int idx = tid + l * THREADS;
            int ar  = idx / (BK / 4);
            int ac  = (idx % (BK / 4)) * 4;
            float4 v = make_float4(0.f, 0.f, 0.f, 0.f);
            int gr = rowBase + ar;
            if (gr < M)
                v = *reinterpret_cast<const float4*>(&A[(size_t)gr * K + k0 + ac]);
            if (RELU) {
                v.x = fmaxf(v.x, 0.f); v.y = fmaxf(v.y, 0.f);
                v.z = fmaxf(v.z, 0.f); v.w = fmaxf(v.w, 0.f);
            }
            As[ac + 0][ar] = v.x; As[ac + 1][ar] = v.y;
            As[ac + 2][ar] = v.z; As[ac + 3][ar] = v.w;
        }
        constexpr int BVEC = BK * BN / 4;
        #pragma unroll
        for (int l = 0; l < BVEC / THREADS; l++) {
            int idx = tid + l * THREADS;
            int br  = idx / (BN / 4);
            int bc  = (idx % (BN / 4)) * 4;
            float4 v = *reinterpret_cast<const float4*>(&B[(size_t)(k0 + br) * N + colBase + bc]);
            *reinterpret_cast<float4*>(&Bs[br][bc]) = v;
        }
        __syncthreads();

        #pragma unroll
        for (int kk = 0; kk < BK; kk++) {
            float a[TM], b[TN];
            #pragma unroll
            for (int i = 0; i < TM; i++) a[i] = As[kk][ty * TM + i];
            #pragma unroll
            for (int j = 0; j < TN; j++) b[j] = Bs[kk][tx * TN + j];
            #pragma unroll
            for (int i = 0; i < TM; i++)
                #pragma unroll
                for (int j = 0; j < TN; j++)
                    acc[i][j] = fmaf(a[i], b[j], acc[i][j]);
        }
        __syncthreads();
    }

    #pragma unroll
    for (int i = 0; i < TM; i++) {
        int gr = rowBase + ty * TM + i;
        if (gr >= M) continue;
        #pragma unroll
        for (int j = 0; j < TN; j += 4) {
            float4 v = make_float4(acc[i][j], acc[i][j+1], acc[i][j+2], acc[i][j+3]);
            *reinterpret_cast<float4*>(&C[(size_t)gr * N + colBase + tx * TN + j]) = v;
        }
    }
}

// ---------------------------------------------------------------------------
// out[i,:] = h[i,:] * dinv[i]^2 + b[:]      (self-loop + bias init)
// ---------------------------------------------------------------------------
template<int C>
__global__ void k_self_bias(const float* __restrict__ h, const float* __restrict__ dinv,
                            const float* __restrict__ b, float* __restrict__ out, int n)
{
    int idx = blockIdx.x * blockDim.x + threadIdx.x;
    int total = n * (C / 4);
    if (idx >= total) return;
    int row = idx / (C / 4);
    int c4  = idx % (C / 4);
    float s = dinv[row]; s *= s;
    float4 hv = reinterpret_cast<const float4*>(h)[idx];
    float4 bv = reinterpret_cast<const float4*>(b)[c4];
    float4 o;
    o.x = fmaf(hv.x, s, bv.x); o.y = fmaf(hv.y, s, bv.y);
    o.z = fmaf(hv.z, s, bv.z); o.w = fmaf(hv.w, s, bv.w);
    reinterpret_cast<float4*>(out)[idx] = o;
}

// ---------------------------------------------------------------------------
// Edge scatter: out[dst,:] += h[src,:] * norm[e]
// LPE lanes cooperate per edge; float4 gathers, scalar RED scatters.
// ---------------------------------------------------------------------------
template<int C, int LPE>
__global__ void k_scatter(const int* __restrict__ src, const int* __restrict__ dst,
                          const float* __restrict__ norm, const float* __restrict__ h,
                          float* __restrict__ out, int E)
{
    int gtid = blockIdx.x * blockDim.x + threadIdx.x;
    int e = gtid / LPE;
    int l = gtid % LPE;
    if (e >= E) return;
    int s   = src[e];
    int d   = dst[e];
    float w = norm[e];
    const float4* hs = reinterpret_cast<const float4*>(h + (size_t)s * C);
    float*        ob = out + (size_t)d * C;
    constexpr int V = C / 4 / LPE;
    #pragma unroll
    for (int i = 0; i < V; i++) {
        int f = l + i * LPE;
        float4 v = hs[f];
        atomicAdd(ob + f * 4 + 0, v.x * w);
        atomicAdd(ob + f * 4 + 1, v.y * w);
        atomicAdd(ob + f * 4 + 2, v.z * w);
        atomicAdd(ob + f * 4 + 3, v.w * w);
    }
}

// ---------------------------------------------------------------------------
// In-place log_softmax over rows of 64. One warp per row.
// ---------------------------------------------------------------------------
__global__ void k_logsoftmax64(float* __restrict__ out, int n)
{
    int warp = (blockIdx.x * blockDim.x + threadIdx.x) >> 5;
    int lane = threadIdx.x & 31;
    if (warp >= n) return;
    float* row = out + (size_t)warp * 64;
    float v0 = row[lane];
    float v1 = row[lane + 32];
    float m = fmaxf(v0, v1);
    #pragma unroll
    for (int o = 16; o; o >>= 1) m = fmaxf(m, __shfl_xor_sync(0xFFFFFFFFu, m, o));
    float sum = expf(v0 - m) + expf(v1 - m);
    #pragma unroll
    for (int o = 16; o; o >>= 1) sum += __shfl_xor_sync(0xFFFFFFFFu, sum, o);
    float lg = m + logf(sum);
    row[lane]      = v0 - lg;
    row[lane + 32] = v1 - lg;
}

// ---------------------------------------------------------------------------
// Launch
// ---------------------------------------------------------------------------
extern "C" void kernel_launch(void* const* d_in, const int* in_sizes, int n_in,
                              void* d_out, int out_size)
{
    const float* x  = (const float*)d_in[0];
    const void*  ei = d_in[1];
    const float* W1 = (const float*)d_in[2];
    const float* b1 = (const float*)d_in[3];
    const float* W2 = (const float*)d_in[4];
    const float* b2 = (const float*)d_in[5];
    float* out = (float*)d_out;

    const int n = NODES;
    const int E = in_sizes[1] / 2;

    int *src, *dst;
    float *normv, *deg, *dinv, *h1, *out1, *h2;
    cudaGetSymbolAddress((void**)&src,   g_src);
    cudaGetSymbolAddress((void**)&dst,   g_dst);
    cudaGetSymbolAddress((void**)&normv, g_norm);
    cudaGetSymbolAddress((void**)&deg,   g_deg);
    cudaGetSymbolAddress((void**)&dinv,  g_dinv);
    cudaGetSymbolAddress((void**)&h1,    g_h1);
    cudaGetSymbolAddress((void**)&out1,  g_out1);
    cudaGetSymbolAddress((void**)&h2,    g_h2);

    // 0) normalize edge indices to int32
    k_detect <<<1, 1>>>(ei, E, n);
    k_convert<<<(E + 255) / 256, 256>>>(ei, E);

    // 1) degrees, dinv, per-edge norm
    k_deg_init <<<(n + 255) / 256, 256>>>(deg, n);
    k_deg_count<<<(E + 255) / 256, 256>>>(dst, E, deg);
    k_dinv     <<<(n + 255) / 256, 256>>>(deg, dinv, n);
    k_norm     <<<(E + 255) / 256, 256>>>(src, dst, dinv, normv, E);

    // 2) h1 = x @ W1
    {
        dim3 grid(HID_C / 64, (n + 127) / 128);
        k_gemm<128, 64, 16, 8, 4, false><<<grid, 256>>>(x, W1, h1, n, HID_C, IN_C);
    }

    // 3) out1 = h1 * dinv^2 + b1 ; scatter edges
    k_self_bias<HID_C><<<(n * (HID_C / 4) + 255) / 256, 256>>>(h1, dinv, b1, out1, n);
    k_scatter<HID_C, 32><<<(int)(((size_t)E * 32 + 255) / 256), 256>>>(src, dst, normv, h1, out1, E);

    // 4) h2 = relu(out1) @ W2   (ReLU fused into A load)
    {
        dim3 grid(OUT_C / 64, (n + 127) / 128);
        k_gemm<128, 64, 16, 8, 4, true><<<grid, 256>>>(out1, W2, h2, n, OUT_C, HID_C);
    }

    // 5) d_out = h2 * dinv^2 + b2 ; scatter edges
    k_self_bias<OUT_C><<<(n * (OUT_C / 4) + 255) / 256, 256>>>(h2, dinv, b2, out, n);
    k_scatter<OUT_C, 16><<<(int)(((size_t)E * 16 + 255) / 256), 256>>>(src, dst, normv, h2, out, E);

    // 6) log_softmax in place
    k_logsoftmax64<<<(n * 32 + 255) / 256, 256>>>(out, n);
}

// round 5
// speedup vs baseline: 1.9574x; 1.9574x over previous
#include <cuda_runtime.h>
#include <math.h>
#include <stdint.h>

// ---------------------------------------------------------------------------
// GCN_47760036331636: 2-layer GCN, CSR-gather aggregation, cp.async GEMM.
//   out1 = relu(agg(x @ W1) + b1)
//   out  = log_softmax(agg(out1 @ W2) + b2)
// agg(h)[i] = sum_{e:dst=i} h[src_e]*dinv[src]*dinv[i] + h[i]*dinv[i]^2
// ---------------------------------------------------------------------------

#define NODES  50000
#define EDGES  800000
#define IN_C   512
#define HID_C  256
#define OUT_C  64

// Scratch (allocation-free: __device__ globals)
__device__ int   g_is64;
__device__ int   g_src [EDGES];
__device__ int   g_dst [EDGES];
__device__ int   g_cnt [NODES];
__device__ int   g_cur [NODES];
__device__ int   g_rs  [NODES + 1];
__device__ int   g_psrc[EDGES];
__device__ float g_pw  [EDGES];
__device__ float g_dinv[NODES];
__device__ float g_h1  [(size_t)NODES * HID_C];   // x @ W1
__device__ float g_out1[(size_t)NODES * HID_C];   // relu(agg layer-1)
__device__ float g_h2  [(size_t)NODES * OUT_C];   // out1 @ W2

// ---------------------------------------------------------------------------
// Edge dtype detection + conversion (int64 vs int32, JAX x64 off -> int32)
// ---------------------------------------------------------------------------
__global__ void k_detect(const void* ei, int E, int n) {
    if (blockIdx.x == 0 && threadIdx.x == 0) {
        const unsigned long long* p = (const unsigned long long*)ei;
        int cnt = E < 1024 ? E : 1024;
        int ok64 = 1;
        for (int i = 0; i < cnt; i++)
            if (p[i] >= (unsigned long long)n) { ok64 = 0; break; }
        g_is64 = ok64;
    }
}

__global__ void k_convert(const void* ei, int E) {
    int e = blockIdx.x * blockDim.x + threadIdx.x;
    if (e >= E) return;
    int s, d;
    if (g_is64) {
        const long long* p = (const long long*)ei;
        s = (int)p[e]; d = (int)p[E + e];
    } else {
        const int* p = (const int*)ei;
        s = p[e]; d = p[E + e];
    }
    g_src[e] = s;
    g_dst[e] = d;
}

// ---------------------------------------------------------------------------
// CSR build: count -> dinv -> scan -> fill
// ---------------------------------------------------------------------------
__global__ void k_zero2(int* a, int* b, int n) {
    int i = blockIdx.x * blockDim.x + threadIdx.x;
    if (i < n) { a[i] = 0; b[i] = 0; }
}

__global__ void k_count(const int* __restrict__ dst, int E, int* cnt) {
    int e = blockIdx.x * blockDim.x + threadIdx.x;
    if (e < E) atomicAdd(cnt + dst[e], 1);
}

__global__ void k_dinv(const int* __restrict__ cnt, float* __restrict__ dinv, int n) {
    int i = blockIdx.x * blockDim.x + threadIdx.x;
    if (i < n) dinv[i] = rsqrtf(1.0f + (float)cnt[i]);   // +1 self-loop
}

// Single-block exclusive scan (1024 threads, sequential 1024-chunks)
__global__ void k_scan(const int* __restrict__ cnt, int* __restrict__ rs, int n) {
    __shared__ int wsum[32];
    __shared__ int carry;
    int tid = threadIdx.x, lane = tid & 31, wid = tid >> 5;
    if (tid == 0) carry = 0;
    __syncthreads();
    for (int base = 0; base < n; base += 1024) {
        int idx = base + tid;
        int v = (idx < n) ? cnt[idx] : 0;
        int x = v;
        #pragma unroll
        for (int o = 1; o < 32; o <<= 1) {
            int t = __shfl_up_sync(0xFFFFFFFFu, x, o);
            if (lane >= o) x += t;
        }
        if (lane == 31) wsum[wid] = x;
        __syncthreads();
        if (wid == 0) {
            int y = wsum[lane];
            #pragma unroll
            for (int o = 1; o < 32; o <<= 1) {
                int t = __shfl_up_sync(0xFFFFFFFFu, y, o);
                if (lane >= o) y += t;
            }
            wsum[lane] = y;
        }
        __syncthreads();
        int excl = carry + x - v + (wid ? wsum[wid - 1] : 0);
        if (idx < n) rs[idx] = excl;
        int total = wsum[31];
        __syncthreads();
        if (tid == 0) carry += total;
        __syncthreads();
    }
    if (tid == 0) rs[n] = carry;
}

__global__ void k_fill(const int* __restrict__ src, const int* __restrict__ dst,
                       const int* __restrict__ rs, int* __restrict__ cur,
                       const float* __restrict__ dinv,
                       int* __restrict__ psrc, float* __restrict__ pw, int E)
{
    int e = blockIdx.x * blockDim.x + threadIdx.x;
    if (e >= E) return;
    int s = src[e], d = dst[e];
    int pos = rs[d] + atomicAdd(cur + d, 1);
    psrc[pos] = s;
    pw[pos]   = dinv[s] * dinv[d];
}

// ---------------------------------------------------------------------------
// Double-buffered cp.async fp32 GEMM: C[M,N] = A[M,K] @ B[K,N]
// BM=128, BK=16, 256 threads. TM=8. (BN,TN) = (128,8) or (64,4).
// ---------------------------------------------------------------------------
#define CP_ASYNC16(dst32, srcp, pbytes) \
    asm volatile("cp.async.cg.shared.global [%0], [%1], 16, %2;" \
                 :: "r"(dst32), "l"(srcp), "r"(pbytes) : "memory")
#define CP_COMMIT()  asm volatile("cp.async.commit_group;" ::: "memory")
#define CP_WAIT(N)   asm volatile("cp.async.wait_group %0;" :: "n"(N) : "memory")

template<int BM, int BN, int BK, int TM, int TN>
__global__ void k_gemm_db(const float* __restrict__ A, const float* __restrict__ B,
                          float* __restrict__ C, int M, int N, int K)
{
    constexpr int THREADS = (BM / TM) * (BN / TN);
    constexpr int APAD = 4;
    __shared__ float As[2][BM][BK + APAD];
    __shared__ float Bs[2][BK][BN];

    const int tid = threadIdx.x;
    const int tx  = tid % (BN / TN);
    const int ty  = tid / (BN / TN);
    const int rowBase = blockIdx.y * BM;
    const int colBase = blockIdx.x * BN;

    constexpr int NA = BM * BK / 4 / THREADS;   // float4 loads of A per thread
    constexpr int NB = BK * BN / 4 / THREADS;

    int a_ar[NA], a_ac[NA];
    #pragma unroll
    for (int l = 0; l < NA; l++) {
        int idx = tid + l * THREADS;
        a_ar[l] = idx / (BK / 4);
        a_ac[l] = (idx % (BK / 4)) * 4;
    }
    int b_br[NB], b_bc[NB];
    #pragma unroll
    for (int l = 0; l < NB; l++) {
        int idx = tid + l * THREADS;
        b_br[l] = idx / (BN / 4);
        b_bc[l] = (idx % (BN / 4)) * 4;
    }

    auto load_tiles = [&](int buf, int k0) {
        #pragma unroll
        for (int l = 0; l < NA; l++) {
            int gr = rowBase + a_ar[l];
            int grc = gr < M ? gr : M - 1;
            const float* src = A + (size_t)grc * K + k0 + a_ac[l];
            uint32_t d = (uint32_t)__cvta_generic_to_shared(&As[buf][a_ar[l]][a_ac[l]]);
            int p = gr < M ? 16 : 0;     // src-size 0 -> zero-fill
            CP_ASYNC16(d, src, p);
        }
        #pragma unroll
        for (int l = 0; l < NB; l++) {
            const float* src = B + (size_t)(k0 + b_br[l]) * N + colBase + b_bc[l];
            uint32_t d = (uint32_t)__cvta_generic_to_shared(&Bs[buf][b_br[l]][b_bc[l]]);
            CP_ASYNC16(d, src, 16);
        }
        CP_COMMIT();
    };

    float acc[TM][TN];
    #pragma unroll
    for (int i = 0; i < TM; i++)
        #pragma unroll
        for (int j = 0; j < TN; j++) acc[i][j] = 0.0f;

    const int nk = K / BK;
    load_tiles(0, 0);

    for (int kt = 0; kt < nk; kt++) {
        int buf = kt & 1;
        if (kt + 1 < nk) {
            load_tiles(buf ^ 1, (kt + 1) * BK);
            CP_WAIT(1);
        } else {
            CP_WAIT(0);
        }
        __syncthreads();

        #pragma unroll
        for (int kk = 0; kk < BK; kk++) {
            float a[TM], b[TN];
            #pragma unroll
            for (int i = 0; i < TM; i++) a[i] = As[buf][ty * TM + i][kk];
            #pragma unroll
            for (int j = 0; j < TN; j += 4) {
                float4 t = *reinterpret_cast<const float4*>(&Bs[buf][kk][tx * TN + j]);
                b[j] = t.x; b[j + 1] = t.y; b[j + 2] = t.z; b[j + 3] = t.w;
            }
            #pragma unroll
            for (int i = 0; i < TM; i++)
                #pragma unroll
                for (int j = 0; j < TN; j++)
                    acc[i][j] = fmaf(a[i], b[j], acc[i][j]);
        }
        __syncthreads();
    }

    #pragma unroll
    for (int i = 0; i < TM; i++) {
        int gr = rowBase + ty * TM + i;
        if (gr >= M) continue;
        #pragma unroll
        for (int j = 0; j < TN; j += 4) {
            float4 v = make_float4(acc[i][j], acc[i][j+1], acc[i][j+2], acc[i][j+3]);
            *reinterpret_cast<float4*>(&C[(size_t)gr * N + colBase + tx * TN + j]) = v;
        }
    }
}

// ---------------------------------------------------------------------------
// CSR aggregation: out[i,:] = maybe_relu( sum_e h[psrc[e],:]*pw[e]
//                                         + h[i,:]*dinv[i]^2 + bias[:] )
// TPN = C/4 threads per node, float4 per thread, 256-thread blocks.
// ---------------------------------------------------------------------------
template<int C, bool RELU>
__global__ void k_agg(const int* __restrict__ rs, const int* __restrict__ psrc,
                      const float* __restrict__ pw, const float* __restrict__ h,
                      const float* __restrict__ dinv, const float* __restrict__ bias,
                      float* __restrict__ out, int n)
{
    constexpr int TPN = C / 4;
    constexpr int NPB = 256 / TPN;
    int sub  = threadIdx.x / TPN;
    int t    = threadIdx.x % TPN;
    int node = blockIdx.x * NPB + sub;
    if (node >= n) return;

    const float4* h4 = reinterpret_cast<const float4*>(h);
    int beg = rs[node], end = rs[node + 1];

    float4 acc = make_float4(0.f, 0.f, 0.f, 0.f);
    for (int e = beg; e < end; e++) {
        int s   = __ldg(psrc + e);
        float w = __ldg(pw + e);
        float4 v = h4[(size_t)s * TPN + t];
        acc.x = fmaf(v.x, w, acc.x);
        acc.y = fmaf(v.y, w, acc.y);
        acc.z = fmaf(v.z, w, acc.z);
        acc.w = fmaf(v.w, w, acc.w);
    }
    float di = dinv[node];
    float s2 = di * di;
    float4 hv = h4[(size_t)node * TPN + t];
    float4 bv = reinterpret_cast<const float4*>(bias)[t];
    float4 o;
    o.x = acc.x + hv.x * s2 + bv.x;
    o.y = acc.y + hv.y * s2 + bv.y;
    o.z = acc.z + hv.z * s2 + bv.z;
    o.w = acc.w + hv.w * s2 + bv.w;
    if (RELU) {
        o.x = fmaxf(o.x, 0.f); o.y = fmaxf(o.y, 0.f);
        o.z = fmaxf(o.z, 0.f); o.w = fmaxf(o.w, 0.f);
    }
    reinterpret_cast<float4*>(out)[(size_t)node * TPN + t] = o;
}

// ---------------------------------------------------------------------------
// In-place log_softmax over rows of 64. One warp per row.
// ---------------------------------------------------------------------------
__global__ void k_logsoftmax64(float* __restrict__ out, int n)
{
    int warp = (blockIdx.x * blockDim.x + threadIdx.x) >> 5;
    int lane = threadIdx.x & 31;
    if (warp >= n) return;
    float* row = out + (size_t)warp * 64;
    float v0 = row[lane];
    float v1 = row[lane + 32];
    float m = fmaxf(v0, v1);
    #pragma unroll
    for (int o = 16; o; o >>= 1) m = fmaxf(m, __shfl_xor_sync(0xFFFFFFFFu, m, o));
    float sum = expf(v0 - m) + expf(v1 - m);
    #pragma unroll
    for (int o = 16; o; o >>= 1) sum += __shfl_xor_sync(0xFFFFFFFFu, sum, o);
    float lg = m + logf(sum);
    row[lane]      = v0 - lg;
    row[lane + 32] = v1 - lg;
}

// ---------------------------------------------------------------------------
// Launch
// ---------------------------------------------------------------------------
extern "C" void kernel_launch(void* const* d_in, const int* in_sizes, int n_in,
                              void* d_out, int out_size)
{
    const float* x  = (const float*)d_in[0];
    const void*  ei = d_in[1];
    const float* W1 = (const float*)d_in[2];
    const float* b1 = (const float*)d_in[3];
    const float* W2 = (const float*)d_in[4];
    const float* b2 = (const float*)d_in[5];
    float* out = (float*)d_out;

    const int n = NODES;
    const int E = in_sizes[1] / 2;

    int *src, *dst, *cnt, *cur, *rs, *psrc;
    float *pw, *dinv, *h1, *out1, *h2;
    cudaGetSymbolAddress((void**)&src,  g_src);
    cudaGetSymbolAddress((void**)&dst,  g_dst);
    cudaGetSymbolAddress((void**)&cnt,  g_cnt);
    cudaGetSymbolAddress((void**)&cur,  g_cur);
    cudaGetSymbolAddress((void**)&rs,   g_rs);
    cudaGetSymbolAddress((void**)&psrc, g_psrc);
    cudaGetSymbolAddress((void**)&pw,   g_pw);
    cudaGetSymbolAddress((void**)&dinv, g_dinv);
    cudaGetSymbolAddress((void**)&h1,   g_h1);
    cudaGetSymbolAddress((void**)&out1, g_out1);
    cudaGetSymbolAddress((void**)&h2,   g_h2);

    // 0) normalize edge indices to int32
    k_detect <<<1, 1>>>(ei, E, n);
    k_convert<<<(E + 255) / 256, 256>>>(ei, E);

    // 1) CSR build
    k_zero2<<<(n + 255) / 256, 256>>>(cnt, cur, n);
    k_count<<<(E + 255) / 256, 256>>>(dst, E, cnt);
    k_dinv <<<(n + 255) / 256, 256>>>(cnt, dinv, n);
    k_scan <<<1, 1024>>>(cnt, rs, n);
    k_fill <<<(E + 255) / 256, 256>>>(src, dst, rs, cur, dinv, psrc, pw, E);

    // 2) h1 = x @ W1
    {
        dim3 grid(HID_C / 128, (n + 127) / 128);
        k_gemm_db<128, 128, 16, 8, 8><<<grid, 256>>>(x, W1, h1, n, HID_C, IN_C);
    }

    // 3) out1 = relu(agg(h1) + b1)
    k_agg<HID_C, true><<<(n + 3) / 4, 256>>>(rs, psrc, pw, h1, dinv, b1, out1, n);

    // 4) h2 = out1 @ W2
    {
        dim3 grid(OUT_C / 64, (n + 127) / 128);
        k_gemm_db<128, 64, 16, 8, 4><<<grid, 256>>>(out1, W2, h2, n, OUT_C, HID_C);
    }

    // 5) d_out = agg(h2) + b2
    k_agg<OUT_C, false><<<(n + 15) / 16, 256>>>(rs, psrc, pw, h2, dinv, b2, out, n);

    // 6) log_softmax in place
    k_logsoftmax64<<<(n * 32 + 255) / 256, 256>>>(out, n);
}

// round 7
// speedup vs baseline: 2.4279x; 1.2404x over previous
#include <cuda_runtime.h>
#include <cuda_bf16.h>
#include <math.h>
#include <stdint.h>

// ---------------------------------------------------------------------------
// GCN_47760036331636: 2-layer GCN.
//   Layer1 GEMM via mma.sync bf16-split (xhi@Whi + xhi@Wlo + xlo@Whi, fp32 acc)
//   (tcgen05 unavailable: harness compiles through compute_100 non-'a' PTX)
//   CSR-gather aggregation, SIMT cp.async GEMM2, fused epilogues.
// ---------------------------------------------------------------------------

#define NODES  50000
#define EDGES  800000
#define IN_C   512
#define HID_C  256
#define OUT_C  64

// Scratch (allocation-free: __device__ globals)
__device__ int   g_is64;
__device__ int   g_src [EDGES];
__device__ int   g_dst [EDGES];
__device__ int   g_cnt [NODES];
__device__ int   g_cur [NODES];
__device__ int   g_rs  [NODES + 1];
__device__ int   g_psrc[EDGES];
__device__ float g_pw  [EDGES];
__device__ float g_dinv[NODES];
__device__ __nv_bfloat16 g_xhi [(size_t)NODES * IN_C];
__device__ __nv_bfloat16 g_xlo [(size_t)NODES * IN_C];
__device__ __nv_bfloat16 g_wthi[(size_t)HID_C * IN_C];   // W1^T, [n][k]
__device__ __nv_bfloat16 g_wtlo[(size_t)HID_C * IN_C];
__device__ float g_h1  [(size_t)NODES * HID_C];
__device__ float g_out1[(size_t)NODES * HID_C];
__device__ float g_h2  [(size_t)NODES * OUT_C];

#define CP_ASYNC16(dst32, srcp, pbytes) \
    asm volatile("cp.async.cg.shared.global [%0], [%1], 16, %2;" \
                 :: "r"(dst32), "l"(srcp), "r"(pbytes) : "memory")
#define CP_COMMIT()  asm volatile("cp.async.commit_group;" ::: "memory")
#define CP_WAIT(N)   asm volatile("cp.async.wait_group %0;" :: "n"(N) : "memory")

// ---------------------------------------------------------------------------
// Edge dtype detection + conversion (int64 vs int32, JAX x64 off -> int32)
// ---------------------------------------------------------------------------
__global__ void k_detect(const void* ei, int E, int n) {
    if (blockIdx.x == 0 && threadIdx.x == 0) {
        const unsigned long long* p = (const unsigned long long*)ei;
        int cnt = E < 1024 ? E : 1024;
        int ok64 = 1;
        for (int i = 0; i < cnt; i++)
            if (p[i] >= (unsigned long long)n) { ok64 = 0; break; }
        g_is64 = ok64;
    }
}

__global__ void k_convert(const void* ei, int E) {
    int e = blockIdx.x * blockDim.x + threadIdx.x;
    if (e >= E) return;
    int s, d;
    if (g_is64) {
        const long long* p = (const long long*)ei;
        s = (int)p[e]; d = (int)p[E + e];
    } else {
        const int* p = (const int*)ei;
        s = p[e]; d = p[E + e];
    }
    g_src[e] = s;
    g_dst[e] = d;
}

// ---------------------------------------------------------------------------
// CSR build: count -> dinv -> scan -> fill
// ---------------------------------------------------------------------------
__global__ void k_zero2(int* a, int* b, int n) {
    int i = blockIdx.x * blockDim.x + threadIdx.x;
    if (i < n) { a[i] = 0; b[i] = 0; }
}

__global__ void k_count(const int* __restrict__ dst, int E, int* cnt) {
    int e = blockIdx.x * blockDim.x + threadIdx.x;
    if (e < E) atomicAdd(cnt + dst[e], 1);
}

__global__ void k_dinv(const int* __restrict__ cnt, float* __restrict__ dinv, int n) {
    int i = blockIdx.x * blockDim.x + threadIdx.x;
    if (i < n) dinv[i] = rsqrtf(1.0f + (float)cnt[i]);
}

__global__ void k_scan(const int* __restrict__ cnt, int* __restrict__ rs, int n) {
    __shared__ int wsum[32];
    __shared__ int carry;
    int tid = threadIdx.x, lane = tid & 31, wid = tid >> 5;
    if (tid == 0) carry = 0;
    __syncthreads();
    for (int base = 0; base < n; base += 1024) {
        int idx = base + tid;
        int v = (idx < n) ? cnt[idx] : 0;
        int x = v;
        #pragma unroll
        for (int o = 1; o < 32; o <<= 1) {
            int t = __shfl_up_sync(0xFFFFFFFFu, x, o);
            if (lane >= o) x += t;
        }
        if (lane == 31) wsum[wid] = x;
        __syncthreads();
        if (wid == 0) {
            int y = wsum[lane];
            #pragma unroll
            for (int o = 1; o < 32; o <<= 1) {
                int t = __shfl_up_sync(0xFFFFFFFFu, y, o);
                if (lane >= o) y += t;
            }
            wsum[lane] = y;
        }
        __syncthreads();
        int excl = carry + x - v + (wid ? wsum[wid - 1] : 0);
        if (idx < n) rs[idx] = excl;
        int total = wsum[31];
        __syncthreads();
        if (tid == 0) carry += total;
        __syncthreads();
    }
    if (tid == 0) rs[n] = carry;
}

__global__ void k_fill(const int* __restrict__ src, const int* __restrict__ dst,
                       const int* __restrict__ rs, int* __restrict__ cur,
                       const float* __restrict__ dinv,
                       int* __restrict__ psrc, float* __restrict__ pw, int E)
{
    int e = blockIdx.x * blockDim.x + threadIdx.x;
    if (e >= E) return;
    int s = src[e], d = dst[e];
    int pos = rs[d] + atomicAdd(cur + d, 1);
    psrc[pos] = s;
    pw[pos]   = dinv[s] * dinv[d];
}

// ---------------------------------------------------------------------------
// bf16 hi/lo split of x; transpose+split of W1
// ---------------------------------------------------------------------------
__global__ void k_split_x(const float* __restrict__ x, __nv_bfloat16* __restrict__ hi,
                          __nv_bfloat16* __restrict__ lo, int total4)
{
    int i = blockIdx.x * blockDim.x + threadIdx.x;
    if (i >= total4) return;
    float4 v = reinterpret_cast<const float4*>(x)[i];
    __nv_bfloat16 h0 = __float2bfloat16(v.x), h1 = __float2bfloat16(v.y);
    __nv_bfloat16 h2 = __float2bfloat16(v.z), h3 = __float2bfloat16(v.w);
    __nv_bfloat16 l0 = __float2bfloat16(v.x - __bfloat162float(h0));
    __nv_bfloat16 l1 = __float2bfloat16(v.y - __bfloat162float(h1));
    __nv_bfloat16 l2 = __float2bfloat16(v.z - __bfloat162float(h2));
    __nv_bfloat16 l3 = __float2bfloat16(v.w - __bfloat162float(h3));
    reinterpret_cast<__nv_bfloat162*>(hi)[i * 2 + 0] = __nv_bfloat162(h0, h1);
    reinterpret_cast<__nv_bfloat162*>(hi)[i * 2 + 1] = __nv_bfloat162(h2, h3);
    reinterpret_cast<__nv_bfloat162*>(lo)[i * 2 + 0] = __nv_bfloat162(l0, l1);
    reinterpret_cast<__nv_bfloat162*>(lo)[i * 2 + 1] = __nv_bfloat162(l2, l3);
}

__global__ void k_split_wt(const float* __restrict__ W, __nv_bfloat16* __restrict__ hi,
                           __nv_bfloat16* __restrict__ lo)
{
    int idx = blockIdx.x * blockDim.x + threadIdx.x;
    if (idx >= HID_C * IN_C) return;
    int k = idx / HID_C, n = idx % HID_C;
    float v = W[idx];
    __nv_bfloat16 h = __float2bfloat16(v);
    hi[(size_t)n * IN_C + k] = h;
    lo[(size_t)n * IN_C + k] = __float2bfloat16(v - __bfloat162float(h));
}

// ---------------------------------------------------------------------------
// mma.sync bf16-split GEMM1: h1[M,256] = x @ W1  (fp32 accumulate)
// 256 threads, block tile 128x128, warps 2(M)x4(N) each 64x32,
// mma m16n8k16, BK=32, double-buffered cp.async.
// ---------------------------------------------------------------------------
#define G1_BK     32
#define G1_SA     40                      // half-stride per row (32 + 8 pad)
#define G1_TILE   (128 * G1_SA)           // halves per tile
#define G1_SMEM   (8 * G1_TILE * 2)       // 81920 bytes

__device__ __forceinline__ uint32_t ld2h(const __nv_bfloat16* base, int row, int col) {
    return *reinterpret_cast<const uint32_t*>(base + row * G1_SA + col);
}
__device__ __forceinline__ void mma_bf16(float* d, const uint32_t* a, const uint32_t* b) {
    asm volatile(
        "mma.sync.aligned.m16n8k16.row.col.f32.bf16.bf16.f32 "
        "{%0,%1,%2,%3}, {%4,%5,%6,%7}, {%8,%9}, {%0,%1,%2,%3};"
        : "+f"(d[0]), "+f"(d[1]), "+f"(d[2]), "+f"(d[3])
        : "r"(a[0]), "r"(a[1]), "r"(a[2]), "r"(a[3]), "r"(b[0]), "r"(b[1]));
}

__global__ void __launch_bounds__(256) k_gemm1_mma(
    const __nv_bfloat16* __restrict__ xhi, const __nv_bfloat16* __restrict__ xlo,
    const __nv_bfloat16* __restrict__ wthi, const __nv_bfloat16* __restrict__ wtlo,
    float* __restrict__ C, int M)
{
    extern __shared__ __nv_bfloat16 sm[];
    // tiles: [buf] AHI, ALO, BHI, BLO
    __nv_bfloat16* AHI[2] = { sm,              sm + G1_TILE     };
    __nv_bfloat16* ALO[2] = { sm + 2*G1_TILE,  sm + 3*G1_TILE   };
    __nv_bfloat16* BHI[2] = { sm + 4*G1_TILE,  sm + 5*G1_TILE   };
    __nv_bfloat16* BLO[2] = { sm + 6*G1_TILE,  sm + 7*G1_TILE   };

    const int tid  = threadIdx.x;
    const int warp = tid >> 5, lane = tid & 31;
    const int qr = lane >> 2, qc = lane & 3;
    const int wm0 = (warp >> 2) * 64;       // warp M offset (0 or 64)
    const int wn0 = (warp & 3) * 32;        // warp N offset (0,32,64,96)
    const int mBase   = blockIdx.y * 128;
    const int colBase = blockIdx.x * 128;

    // cp.async loader: tile 128 rows x 32 halves = 128x4 16B chunks; 512/256=2 per thr
    auto load_stage = [&](int buf, int k0) {
        #pragma unroll
        for (int l = 0; l < 2; l++) {
            int idx = tid + l * 256;
            int r = idx >> 2, ch = idx & 3;
            uint32_t soff = (uint32_t)((r * G1_SA + ch * 8) * 2);
            // A (hi/lo): row = mBase + r
            int gm  = mBase + r;
            int gmc = gm < M ? gm : M - 1;
            int p   = gm < M ? 16 : 0;
            const __nv_bfloat16* sa_hi = xhi + (size_t)gmc * IN_C + k0 + ch * 8;
            const __nv_bfloat16* sa_lo = xlo + (size_t)gmc * IN_C + k0 + ch * 8;
            CP_ASYNC16((uint32_t)__cvta_generic_to_shared(AHI[buf]) + soff, sa_hi, p);
            CP_ASYNC16((uint32_t)__cvta_generic_to_shared(ALO[buf]) + soff, sa_lo, p);
            // B (hi/lo): wt row = colBase + r  (HID_C=256, always in range)
            const __nv_bfloat16* sb_hi = wthi + (size_t)(colBase + r) * IN_C + k0 + ch * 8;
            const __nv_bfloat16* sb_lo = wtlo + (size_t)(colBase + r) * IN_C + k0 + ch * 8;
            CP_ASYNC16((uint32_t)__cvta_generic_to_shared(BHI[buf]) + soff, sb_hi, 16);
            CP_ASYNC16((uint32_t)__cvta_generic_to_shared(BLO[buf]) + soff, sb_lo, 16);
        }
        CP_COMMIT();
    };

    float acc[4][4][4];
    #pragma unroll
    for (int i = 0; i < 4; i++)
        #pragma unroll
        for (int j = 0; j < 4; j++)
            #pragma unroll
            for (int r = 0; r < 4; r++) acc[i][j][r] = 0.0f;

    const int nk = IN_C / G1_BK;   // 16
    load_stage(0, 0);

    for (int kt = 0; kt < nk; kt++) {
        int buf = kt & 1;
        if (kt + 1 < nk) { load_stage(buf ^ 1, (kt + 1) * G1_BK); CP_WAIT(1); }
        else             { CP_WAIT(0); }
        __syncthreads();

        #pragma unroll
        for (int ks = 0; ks < 2; ks++) {
            const int kh = ks * 16;
            uint32_t ahi[4][4], alo[4][4], bhi[4][2], blo[4][2];
            #pragma unroll
            for (int i = 0; i < 4; i++) {
                int r0 = wm0 + i * 16 + qr;
                int c0 = kh + qc * 2;
                ahi[i][0] = ld2h(AHI[buf], r0,     c0);
                ahi[i][1] = ld2h(AHI[buf], r0 + 8, c0);
                ahi[i][2] = ld2h(AHI[buf], r0,     c0 + 8);
                ahi[i][3] = ld2h(AHI[buf], r0 + 8, c0 + 8);
                alo[i][0] = ld2h(ALO[buf], r0,     c0);
                alo[i][1] = ld2h(ALO[buf], r0 + 8, c0);
                alo[i][2] = ld2h(ALO[buf], r0,     c0 + 8);
                alo[i][3] = ld2h(ALO[buf], r0 + 8, c0 + 8);
            }
            #pragma unroll
            for (int j = 0; j < 4; j++) {
                int nr = wn0 + j * 8 + qr;
                int c0 = kh + qc * 2;
                bhi[j][0] = ld2h(BHI[buf], nr, c0);
                bhi[j][1] = ld2h(BHI[buf], nr, c0 + 8);
                blo[j][0] = ld2h(BLO[buf], nr, c0);
                blo[j][1] = ld2h(BLO[buf], nr, c0 + 8);
            }
            #pragma unroll
            for (int i = 0; i < 4; i++)
                #pragma unroll
                for (int j = 0; j < 4; j++) {
                    mma_bf16(acc[i][j], ahi[i], bhi[j]);
                    mma_bf16(acc[i][j], ahi[i], blo[j]);
                    mma_bf16(acc[i][j], alo[i], bhi[j]);
                }
        }
        __syncthreads();
    }

    // Epilogue: c0,c1 -> (row, col..col+1); c2,c3 -> (row+8, col..col+1)
    #pragma unroll
    for (int i = 0; i < 4; i++) {
        int m0 = mBase + wm0 + i * 16 + qr;
        #pragma unroll
        for (int j = 0; j < 4; j++) {
            int nc = colBase + wn0 + j * 8 + qc * 2;
            if (m0 < M)
                *reinterpret_cast<float2*>(C + (size_t)m0 * HID_C + nc) =
                    make_float2(acc[i][j][0], acc[i][j][1]);
            if (m0 + 8 < M)
                *reinterpret_cast<float2*>(C + (size_t)(m0 + 8) * HID_C + nc) =
                    make_float2(acc[i][j][2], acc[i][j][3]);
        }
    }
}

// ---------------------------------------------------------------------------
// Double-buffered cp.async fp32 GEMM (layer 2)
// ---------------------------------------------------------------------------
template<int BM, int BN, int BK, int TM, int TN>
__global__ void k_gemm_db(const float* __restrict__ A, const float* __restrict__ B,
                          float* __restrict__ C, int M, int N, int K)
{
    constexpr int THREADS = (BM / TM) * (BN / TN);
    constexpr int APAD = 4;
    __shared__ float As[2][BM][BK + APAD];
    __shared__ float Bs[2][BK][BN];

    const int tid = threadIdx.x;
    const int tx  = tid % (BN / TN);
    const int ty  = tid / (BN / TN);
    const int rowBase = blockIdx.y * BM;
    const int colBase = blockIdx.x * BN;

    constexpr int NA = BM * BK / 4 / THREADS;
    constexpr int NB = BK * BN / 4 / THREADS;

    int a_ar[NA], a_ac[NA];
    #pragma unroll
    for (int l = 0; l < NA; l++) {
        int idx = tid + l * THREADS;
        a_ar[l] = idx / (BK / 4);
        a_ac[l] = (idx % (BK / 4)) * 4;
    }
    int b_br[NB], b_bc[NB];
    #pragma unroll
    for (int l = 0; l < NB; l++) {
        int idx = tid + l * THREADS;
        b_br[l] = idx / (BN / 4);
        b_bc[l] = (idx % (BN / 4)) * 4;
    }

    auto load_tiles = [&](int buf, int k0) {
        #pragma unroll
        for (int l = 0; l < NA; l++) {
            int gr = rowBase + a_ar[l];
            int grc = gr < M ? gr : M - 1;
            const float* src = A + (size_t)grc * K + k0 + a_ac[l];
            uint32_t d = (uint32_t)__cvta_generic_to_shared(&As[buf][a_ar[l]][a_ac[l]]);
            int p = gr < M ? 16 : 0;
            CP_ASYNC16(d, src, p);
        }
        #pragma unroll
        for (int l = 0; l < NB; l++) {
            const float* src = B + (size_t)(k0 + b_br[l]) * N + colBase + b_bc[l];
            uint32_t d = (uint32_t)__cvta_generic_to_shared(&Bs[buf][b_br[l]][b_bc[l]]);
            CP_ASYNC16(d, src, 16);
        }
        CP_COMMIT();
    };

    float acc[TM][TN];
    #pragma unroll
    for (int i = 0; i < TM; i++)
        #pragma unroll
        for (int j = 0; j < TN; j++) acc[i][j] = 0.0f;

    const int nk = K / BK;
    load_tiles(0, 0);

    for (int kt = 0; kt < nk; kt++) {
        int buf = kt & 1;
        if (kt + 1 < nk) { load_tiles(buf ^ 1, (kt + 1) * BK); CP_WAIT(1); }
        else             { CP_WAIT(0); }
        __syncthreads();

        #pragma unroll
        for (int kk = 0; kk < BK; kk++) {
            float a[TM], b[TN];
            #pragma unroll
            for (int i = 0; i < TM; i++) a[i] = As[buf][ty * TM + i][kk];
            #pragma unroll
            for (int j = 0; j < TN; j += 4) {
                float4 t = *reinterpret_cast<const float4*>(&Bs[buf][kk][tx * TN + j]);
                b[j] = t.x; b[j + 1] = t.y; b[j + 2] = t.z; b[j + 3] = t.w;
            }
            #pragma unroll
            for (int i = 0; i < TM; i++)
                #pragma unroll
                for (int j = 0; j < TN; j++)
                    acc[i][j] = fmaf(a[i], b[j], acc[i][j]);
        }
        __syncthreads();
    }

    #pragma unroll
    for (int i = 0; i < TM; i++) {
        int gr = rowBase + ty * TM + i;
        if (gr >= M) continue;
        #pragma unroll
        for (int j = 0; j < TN; j += 4) {
            float4 v = make_float4(acc[i][j], acc[i][j+1], acc[i][j+2], acc[i][j+3]);
            *reinterpret_cast<float4*>(&C[(size_t)gr * N + colBase + tx * TN + j]) = v;
        }
    }
}

// ---------------------------------------------------------------------------
// CSR aggregation: out[i,:] = maybe_relu( sum_e h[psrc[e],:]*pw[e]
//                                         + h[i,:]*dinv[i]^2 + bias[:] )
// ---------------------------------------------------------------------------
template<int C, bool RELU>
__global__ void k_agg(const int* __restrict__ rs, const int* __restrict__ psrc,
                      const float* __restrict__ pw, const float* __restrict__ h,
                      const float* __restrict__ dinv, const float* __restrict__ bias,
                      float* __restrict__ out, int n)
{
    constexpr int TPN = C / 4;
    constexpr int NPB = 256 / TPN;
    int sub  = threadIdx.x / TPN;
    int t    = threadIdx.x % TPN;
    int node = blockIdx.x * NPB + sub;
    if (node >= n) return;

    const float4* h4 = reinterpret_cast<const float4*>(h);
    int beg = rs[node], end = rs[node + 1];

    float4 acc = make_float4(0.f, 0.f, 0.f, 0.f);
    for (int e = beg; e < end; e++) {
        int s   = __ldg(psrc + e);
        float w = __ldg(pw + e);
        float4 v = h4[(size_t)s * TPN + t];
        acc.x = fmaf(v.x, w, acc.x);
        acc.y = fmaf(v.y, w, acc.y);
        acc.z = fmaf(v.z, w, acc.z);
        acc.w = fmaf(v.w, w, acc.w);
    }
    float di = dinv[node];
    float s2 = di * di;
    float4 hv = h4[(size_t)node * TPN + t];
    float4 bv = reinterpret_cast<const float4*>(bias)[t];
    float4 o;
    o.x = acc.x + hv.x * s2 + bv.x;
    o.y = acc.y + hv.y * s2 + bv.y;
    o.z = acc.z + hv.z * s2 + bv.z;
    o.w = acc.w + hv.w * s2 + bv.w;
    if (RELU) {
        o.x = fmaxf(o.x, 0.f); o.y = fmaxf(o.y, 0.f);
        o.z = fmaxf(o.z, 0.f); o.w = fmaxf(o.w, 0.f);
    }
    reinterpret_cast<float4*>(out)[(size_t)node * TPN + t] = o;
}

// ---------------------------------------------------------------------------
// In-place log_softmax over rows of 64. One warp per row.
// ---------------------------------------------------------------------------
__global__ void k_logsoftmax64(float* __restrict__ out, int n)
{
    int warp = (blockIdx.x * blockDim.x + threadIdx.x) >> 5;
    int lane = threadIdx.x & 31;
    if (warp >= n) return;
    float* row = out + (size_t)warp * 64;
    float v0 = row[lane];
    float v1 = row[lane + 32];
    float m = fmaxf(v0, v1);
    #pragma unroll
    for (int o = 16; o; o >>= 1) m = fmaxf(m, __shfl_xor_sync(0xFFFFFFFFu, m, o));
    float sum = expf(v0 - m) + expf(v1 - m);
    #pragma unroll
    for (int o = 16; o; o >>= 1) sum += __shfl_xor_sync(0xFFFFFFFFu, sum, o);
    float lg = m + logf(sum);
    row[lane]      = v0 - lg;
    row[lane + 32] = v1 - lg;
}

// ---------------------------------------------------------------------------
// Launch
// ---------------------------------------------------------------------------
extern "C" void kernel_launch(void* const* d_in, const int* in_sizes, int n_in,
                              void* d_out, int out_size)
{
    const float* x  = (const float*)d_in[0];
    const void*  ei = d_in[1];
    const float* W1 = (const float*)d_in[2];
    const float* b1 = (const float*)d_in[3];
    const float* W2 = (const float*)d_in[4];
    const float* b2 = (const float*)d_in[5];
    float* out = (float*)d_out;

    const int n = NODES;
    const int E = in_sizes[1] / 2;

    int *src, *dst, *cnt, *cur, *rs, *psrc;
    float *pw, *dinv, *h1, *out1, *h2;
    __nv_bfloat16 *xhi, *xlo, *wthi, *wtlo;
    cudaGetSymbolAddress((void**)&src,  g_src);
    cudaGetSymbolAddress((void**)&dst,  g_dst);
    cudaGetSymbolAddress((void**)&cnt,  g_cnt);
    cudaGetSymbolAddress((void**)&cur,  g_cur);
    cudaGetSymbolAddress((void**)&rs,   g_rs);
    cudaGetSymbolAddress((void**)&psrc, g_psrc);
    cudaGetSymbolAddress((void**)&pw,   g_pw);
    cudaGetSymbolAddress((void**)&dinv, g_dinv);
    cudaGetSymbolAddress((void**)&h1,   g_h1);
    cudaGetSymbolAddress((void**)&out1, g_out1);
    cudaGetSymbolAddress((void**)&h2,   g_h2);
    cudaGetSymbolAddress((void**)&xhi,  g_xhi);
    cudaGetSymbolAddress((void**)&xlo,  g_xlo);
    cudaGetSymbolAddress((void**)&wthi, g_wthi);
    cudaGetSymbolAddress((void**)&wtlo, g_wtlo);

    static int smem_set = 0;
    if (!smem_set) {
        cudaFuncSetAttribute(k_gemm1_mma, cudaFuncAttributeMaxDynamicSharedMemorySize,
                             G1_SMEM);
        smem_set = 1;
    }

    // 0) normalize edge indices; split x and W1^T to bf16 hi/lo
    k_detect  <<<1, 1>>>(ei, E, n);
    k_convert <<<(E + 255) / 256, 256>>>(ei, E);
    k_split_x <<<(n * (IN_C / 4) + 255) / 256, 256>>>(x, xhi, xlo, n * (IN_C / 4));
    k_split_wt<<<(HID_C * IN_C + 255) / 256, 256>>>(W1, wthi, wtlo);

    // 1) CSR build
    k_zero2<<<(n + 255) / 256, 256>>>(cnt, cur, n);
    k_count<<<(E + 255) / 256, 256>>>(dst, E, cnt);
    k_dinv <<<(n + 255) / 256, 256>>>(cnt, dinv, n);
    k_scan <<<1, 1024>>>(cnt, rs, n);
    k_fill <<<(E + 255) / 256, 256>>>(src, dst, rs, cur, dinv, psrc, pw, E);

    // 2) h1 = x @ W1 via mma.sync bf16-split
    {
        dim3 grid(HID_C / 128, (n + 127) / 128);
        k_gemm1_mma<<<grid, 256, G1_SMEM>>>(xhi, xlo, wthi, wtlo, h1, n);
    }

    // 3) out1 = relu(agg(h1) + b1)
    k_agg<HID_C, true><<<(n + 3) / 4, 256>>>(rs, psrc, pw, h1, dinv, b1, out1, n);

    // 4) h2 = out1 @ W2
    {
        dim3 grid(OUT_C / 64, (n + 127) / 128);
        k_gemm_db<128, 64, 16, 8, 4><<<grid, 256>>>(out1, W2, h2, n, OUT_C, HID_C);
    }

    // 5) d_out = agg(h2) + b2
    k_agg<OUT_C, false><<<(n + 15) / 16, 256>>>(rs, psrc, pw, h2, dinv, b2, out, n);

    // 6) log_softmax in place
    k_logsoftmax64<<<(n * 32 + 255) / 256, 256>>>(out, n);
}